// round 16
// baseline (speedup 1.0000x reference)
#include <cuda_runtime.h>
#include <cuda_fp16.h>
#include <math.h>
#include <stdint.h>

#define BB 4
#define TT 2048
#define DD 1024
#define EE 8
#define FF 1024
#define NTOK (BB*TT)           // 8192
#define NASG (NTOK*2)          // 16384
#define MAXA (NASG + EE*128)   // 17408
#define MTILES (MAXA/128)      // 136

#define ROUTER_BLOCKS (NTOK/8)            // 1024
#define CVT_GU_BLOCKS ((1 << 21) / 256)   // 8192 (wg+wu: 2^21 uint4 items)

// ff1 aux: zero out (2^21 uint4) + convert wd (2^20 uint4) = 3*2^20 items
#define AUX_ITEMS     (3 << 20)
#define AUX_PER_BLOCK 2048                // 256 threads x 8
#define AUX_BLOCKS    (AUX_ITEMS / AUX_PER_BLOCK)   // 1536
#define AUX_Y         (AUX_BLOCKS / 16)             // 96 extra grid.y rows

// ---------------- scratch (zero-initialized at module load) ----------------
__device__ int   g_counts[EE];
__device__ int   g_cursor[EE];
__device__ int   g_offsets[EE+1];
__device__ int   g_eidx[NASG];
__device__ float g_ew[NASG];
__device__ int   g_token_of[MAXA];     // padded rows stay 0 forever
__device__ float g_weight_of[MAXA];    // padded rows stay 0.0f forever
__device__ int   g_done;

// ---------------- PTX helpers ----------------
__device__ __forceinline__ uint32_t s2u(const void* p) {
    uint32_t a;
    asm("{ .reg .u64 t; cvta.to.shared.u64 t, %1; cvt.u32.u64 %0, t; }" : "=r"(a) : "l"(p));
    return a;
}
#define CP16(dst, src) \
    asm volatile("cp.async.cg.shared.global [%0], [%1], 16;" :: "r"(dst), "l"(src) : "memory")
#define CP_COMMIT() asm volatile("cp.async.commit_group;" ::: "memory")
#define CP_WAIT(N)  asm volatile("cp.async.wait_group %0;" :: "n"(N) : "memory")

#define LDSM4(r0, r1, r2, r3, a) \
    asm volatile("ldmatrix.sync.aligned.m8n8.x4.shared.b16 {%0,%1,%2,%3}, [%4];" \
        : "=r"(r0), "=r"(r1), "=r"(r2), "=r"(r3) : "r"(a))
#define LDSM4T(r0, r1, r2, r3, a) \
    asm volatile("ldmatrix.sync.aligned.m8n8.x4.trans.shared.b16 {%0,%1,%2,%3}, [%4];" \
        : "=r"(r0), "=r"(r1), "=r"(r2), "=r"(r3) : "r"(a))

// mma m16n8k16 fp16 in, fp32 acc
#define MMA_F16(d, a, b0, b1) \
    asm volatile("mma.sync.aligned.m16n8k16.row.col.f32.f16.f16.f32 " \
        "{%0,%1,%2,%3}, {%4,%5,%6,%7}, {%8,%9}, {%0,%1,%2,%3};" \
        : "+f"((d)[0]), "+f"((d)[1]), "+f"((d)[2]), "+f"((d)[3]) \
        : "r"((a)[0]), "r"((a)[1]), "r"((a)[2]), "r"((a)[3]), \
          "r"(b0), "r"(b1))

__device__ __forceinline__ uint32_t pack_h2(float a, float b) {
    __half2 h = __floats2half2_rn(a, b);
    return *(uint32_t*)&h;
}

__device__ __half g_xh [(size_t)NTOK*DD];
__device__ __half g_wgh[(size_t)EE*DD*FF];
__device__ __half g_wuh[(size_t)EE*DD*FF];
__device__ __half g_wdh[(size_t)EE*FF*DD];
__device__ __half g_h  [(size_t)MAXA*FF];

// ============ prep + router + scatter fused ============
// blocks [0, ROUTER_BLOCKS)     : router + fp16 x emit; LAST one also does
//                                 offsets + scatter + counter reset
// blocks [.., +CVT_GU_BLOCKS)   : wg/wu fp32->fp16, 2 float4 -> 1 uint4
__global__ void __launch_bounds__(256)
prep_router(const float* __restrict__ x,  const float* __restrict__ wr,
            const float* __restrict__ wg, const float* __restrict__ wu) {
    __shared__ float s_wr[DD * EE];   // router blocks only
    __shared__ int s_last;
    int tid = threadIdx.x;

    if (blockIdx.x < ROUTER_BLOCKS) {
        // ---------------- router ----------------
        for (int i = tid; i < DD * EE / 4; i += blockDim.x)
            ((float4*)s_wr)[i] = ((const float4*)wr)[i];
        __syncthreads();

        int warp = tid >> 5, lane = tid & 31;
        int t = blockIdx.x * 8 + warp;
        const float* xr = x + (size_t)t * DD;

        float acc[EE];
#pragma unroll
        for (int e = 0; e < EE; e++) acc[e] = 0.f;
#pragma unroll
        for (int i = 0; i < 8; i++) {
            int d0 = i * 128 + lane * 4;
            float4 xv = *(const float4*)(xr + d0);
            uint2 pk = make_uint2(pack_h2(xv.x, xv.y), pack_h2(xv.z, xv.w));
            *(uint2*)(g_xh + (size_t)t * DD + d0) = pk;

            float xa[4] = { xv.x, xv.y, xv.z, xv.w };
#pragma unroll
            for (int j = 0; j < 4; j++) {
                const float4* wp = (const float4*)(s_wr + (size_t)(d0 + j) * EE);
                float4 w0 = wp[0], w1 = wp[1];
                acc[0] += xa[j] * w0.x;  acc[1] += xa[j] * w0.y;
                acc[2] += xa[j] * w0.z;  acc[3] += xa[j] * w0.w;
                acc[4] += xa[j] * w1.x;  acc[5] += xa[j] * w1.y;
                acc[6] += xa[j] * w1.z;  acc[7] += xa[j] * w1.w;
            }
        }
#pragma unroll
        for (int off = 16; off > 0; off >>= 1)
#pragma unroll
            for (int e = 0; e < EE; e++)
                acc[e] += __shfl_xor_sync(0xffffffffu, acc[e], off);

        if (lane == 0) {
            float m = acc[0];
#pragma unroll
            for (int e = 1; e < EE; e++) m = fmaxf(m, acc[e]);
            float p[EE], s = 0.f;
#pragma unroll
            for (int e = 0; e < EE; e++) { p[e] = expf(acc[e] - m); s += p[e]; }
            float inv = 1.f / s;
#pragma unroll
            for (int e = 0; e < EE; e++) p[e] *= inv;

            int be = 0; float b = p[0];
#pragma unroll
            for (int e = 1; e < EE; e++) if (p[e] > b) { b = p[e]; be = e; }
            int be2 = -1; float b2 = -1.f;
#pragma unroll
            for (int e = 0; e < EE; e++)
                if (e != be && p[e] > b2) { b2 = p[e]; be2 = e; }

            float w0 = 1.f / (1.f + expf(b2 - b));
            float w1 = 1.f - w0;

            g_eidx[2*t]   = be;   g_ew[2*t]   = w0;
            g_eidx[2*t+1] = be2;  g_ew[2*t+1] = w1;
            atomicAdd(&g_counts[be], 1);
            atomicAdd(&g_counts[be2], 1);
        }

        // ------- last-router-block election; winner scatters -------
        __syncthreads();
        if (tid == 0) {
            __threadfence();                       // release our router writes
            int old = atomicAdd(&g_done, 1);
            s_last = (old == ROUTER_BLOCKS - 1);
        }
        __syncthreads();
        if (!s_last) return;

        __threadfence();                           // acquire others' writes
        if (tid == 0) {
            int off = 0;
#pragma unroll
            for (int e = 0; e < EE; e++) {
                g_offsets[e] = off;
                off += (g_counts[e] + 127) & ~127;
            }
            g_offsets[EE] = off;
        }
        __syncthreads();

        for (int i = tid; i < NASG; i += 256) {
            int e = g_eidx[i];
            int pos = atomicAdd(&g_cursor[e], 1);
            int a = g_offsets[e] + pos;
            g_token_of[a] = i >> 1;
            g_weight_of[a] = g_ew[i];
        }
        __syncthreads();
        // reset for next graph replay
        if (tid < EE) { g_counts[tid] = 0; g_cursor[tid] = 0; }
        if (tid == 0) g_done = 0;
    } else {
        // ---------------- wg/wu convert: 2 float4 -> 1 uint4 ----------------
        int idx = (blockIdx.x - ROUTER_BLOCKS) * 256 + tid;   // 0 .. 2^21-1
        int j = idx * 2;
        int region = j >> 21;
        int off = j & ((1 << 21) - 1);
        const float* src = region ? wu : wg;
        __half* dst = region ? g_wuh : g_wgh;
        float4 v0 = ((const float4*)src)[off];
        float4 v1 = ((const float4*)src)[off + 1];
        uint4 pk;
        pk.x = pack_h2(v0.x, v0.y);
        pk.y = pack_h2(v0.z, v0.w);
        pk.z = pack_h2(v1.x, v1.y);
        pk.w = pack_h2(v1.z, v1.w);
        ((uint4*)dst)[off >> 1] = pk;
    }
}

// ======================= ff1 : gate+up grouped GEMM (fp16 mma) ===============
// BM=128, BN=64 (two Bs), BK=32, 4 stages, 256 threads, warp tile 32x32. (R8)
// Extra grid.y rows (>= MTILES) are aux blocks: zero out + convert wd.
#define F1_STAGE 19456
#define F1_BOFF  10240

__global__ void __launch_bounds__(256, 2)
ff1_tc(const __half* __restrict__ xh,
       const __half* __restrict__ wgh,
       const __half* __restrict__ wuh,
       const float* __restrict__ wd,
       float* __restrict__ out) {
    int tid = threadIdx.x;

    // ---------------- aux blocks: zero out + wd fp32->fp16 ----------------
    if (blockIdx.y >= MTILES) {
        int bid = (blockIdx.y - MTILES) * gridDim.x + blockIdx.x;   // 0..1535
        int base = bid * AUX_PER_BLOCK + tid;
        const int OUTI = 1 << 21;   // out uint4 items
#pragma unroll
        for (int q = 0; q < 8; q++) {
            int item = base + q * 256;
            if (item < OUTI) {
                ((uint4*)out)[item] = make_uint4(0u, 0u, 0u, 0u);
            } else {
                int u = item - OUTI;            // 0 .. 2^20-1 : uint4 in g_wdh
                int off = u * 2;                // float4 index in wd
                float4 v0 = ((const float4*)wd)[off];
                float4 v1 = ((const float4*)wd)[off + 1];
                uint4 pk;
                pk.x = pack_h2(v0.x, v0.y);
                pk.y = pack_h2(v0.z, v0.w);
                pk.z = pack_h2(v1.x, v1.y);
                pk.w = pack_h2(v1.z, v1.w);
                ((uint4*)g_wdh)[u] = pk;
            }
        }
        return;
    }

    extern __shared__ char smem[];
    int m0 = blockIdx.y * 128;
    if (m0 >= g_offsets[EE]) return;
    int e = 0;
#pragma unroll
    for (int i = 0; i < EE; i++) if (m0 >= g_offsets[i+1]) e = i + 1;
    int n0 = blockIdx.x * 64;

    int wid = tid >> 5, lane = tid & 31;
    int wm = wid & 3, wn = wid >> 2;
    int ly = lane >> 2, lx = lane & 3;
    uint32_t sb = s2u(smem);

    int ar = tid >> 1, ah = tid & 1;
    int tok = g_token_of[m0 + ar];
    const char* aSrc = (const char*)(xh + (size_t)tok * DD) + ah * 32;
    uint32_t aDst = (uint32_t)(ar * 80 + ah * 32);
    const char* gBase = (const char*)(wgh + ((size_t)e << 20) + n0);
    const char* uBase = (const char*)(wuh + ((size_t)e << 20) + n0);
    int id0 = tid, id1 = tid + 256;
    int brow0 = id0 >> 3, bc0 = (id0 & 7) * 16;
    int brow1 = id1 >> 3, bc1 = (id1 & 7) * 16;
    int bmat0 = brow0 >> 5, bk0 = brow0 & 31;
    int bmat1 = brow1 >> 5, bk1 = brow1 & 31;
    const char* bsrc0 = (bmat0 ? uBase : gBase) + bc0;
    const char* bsrc1 = (bmat1 ? uBase : gBase) + bc1;
    uint32_t bdst0 = (uint32_t)(F1_BOFF + bmat0 * 4608 + bk0 * 144 + bc0);
    uint32_t bdst1 = (uint32_t)(F1_BOFF + bmat1 * 4608 + bk1 * 144 + bc1);

    float accG[2][4][4], accU[2][4][4];
#pragma unroll
    for (int a = 0; a < 2; a++)
#pragma unroll
        for (int b = 0; b < 4; b++)
#pragma unroll
            for (int c = 0; c < 4; c++) { accG[a][b][c] = 0.f; accU[a][b][c] = 0.f; }

#define F1_LOAD(kt, slot) do { \
    uint32_t s_ = sb + (slot) * F1_STAGE; \
    const char* as_ = aSrc + (kt) * 64; \
    CP16(s_ + aDst, as_);  CP16(s_ + aDst + 16, as_ + 16); \
    CP16(s_ + bdst0, bsrc0 + (size_t)((kt) * 32 + bk0) * 2048); \
    CP16(s_ + bdst1, bsrc1 + (size_t)((kt) * 32 + bk1) * 2048); \
    CP_COMMIT(); \
} while (0)

    F1_LOAD(0, 0);
    F1_LOAD(1, 1);
    F1_LOAD(2, 2);

    uint32_t l16 = (uint32_t)(lane & 15), lh = (uint32_t)(lane >> 4) * 16;

    const int NIT = DD / 32;
#pragma unroll 1
    for (int kt = 0; kt < NIT; kt++) {
        if (kt < NIT - 2)       { CP_WAIT(2); }
        else if (kt == NIT - 2) { CP_WAIT(1); }
        else                    { CP_WAIT(0); }
        __syncthreads();
        if (kt + 3 < NIT) F1_LOAD(kt + 3, (kt + 3) & 3);

        uint32_t stg = sb + (kt & 3) * F1_STAGE;
#pragma unroll
        for (int ks = 0; ks < 2; ks++) {
            uint32_t a_fr[2][4];
#pragma unroll
            for (int mt = 0; mt < 2; mt++) {
                uint32_t aa = stg + (wm * 32 + mt * 16 + l16) * 80 + ks * 32 + lh;
                LDSM4(a_fr[mt][0], a_fr[mt][1], a_fr[mt][2], a_fr[mt][3], aa);
            }
#pragma unroll
            for (int nt = 0; nt < 2; nt++) {
                uint32_t bg = stg + F1_BOFF + (ks * 16 + l16) * 144 +
                              (wn * 32 + nt * 16) * 2 + lh;
                uint32_t g0, g1, g2, g3, u0, u1, u2, u3;
                LDSM4T(g0, g1, g2, g3, bg);
                LDSM4T(u0, u1, u2, u3, bg + 4608);
#pragma unroll
                for (int mt = 0; mt < 2; mt++) {
                    MMA_F16(accG[mt][nt*2],   a_fr[mt], g0, g1);
                    MMA_F16(accG[mt][nt*2+1], a_fr[mt], g2, g3);
                    MMA_F16(accU[mt][nt*2],   a_fr[mt], u0, u1);
                    MMA_F16(accU[mt][nt*2+1], a_fr[mt], u2, u3);
                }
            }
        }
    }

    // epilogue: h = w * silu(g) * u -> fp16 (w = 0 on padded rows -> h = 0)
#pragma unroll
    for (int mt = 0; mt < 2; mt++) {
        int r0 = m0 + wm * 32 + mt * 16 + ly;
        float w0 = g_weight_of[r0], w1 = g_weight_of[r0 + 8];
#pragma unroll
        for (int nt = 0; nt < 4; nt++) {
            int c = n0 + wn * 32 + nt * 8 + 2 * lx;
            float* G = accG[mt][nt];
            float* U = accU[mt][nt];
            float h0 = w0 * (G[0] / (1.f + __expf(-G[0]))) * U[0];
            float h1 = w0 * (G[1] / (1.f + __expf(-G[1]))) * U[1];
            float h2 = w1 * (G[2] / (1.f + __expf(-G[2]))) * U[2];
            float h3 = w1 * (G[3] / (1.f + __expf(-G[3]))) * U[3];
            *(__half2*)(g_h + (size_t)r0 * FF + c)       = __floats2half2_rn(h0, h1);
            *(__half2*)(g_h + (size_t)(r0 + 8) * FF + c) = __floats2half2_rn(h2, h3);
        }
    }
}

// ======================= ff2 : down grouped GEMM (fp16 mma) ==================
// BM=128, BN=128, BK=32, 4 stages, warp tile 32x64. RED epilogue into out. (R8)
#define F2_STAGE 18944
#define F2_BOFF  10240

__global__ void __launch_bounds__(256, 2)
ff2_tc(const __half* __restrict__ wdh, float* __restrict__ out) {
    extern __shared__ char smem[];
    int m0 = blockIdx.y * 128;
    if (m0 >= g_offsets[EE]) return;
    int e = 0;
#pragma unroll
    for (int i = 0; i < EE; i++) if (m0 >= g_offsets[i+1]) e = i + 1;
    int n0 = blockIdx.x * 128;

    int tid = threadIdx.x, wid = tid >> 5, lane = tid & 31;
    int wm = wid & 3, wn = wid >> 2;
    int ly = lane >> 2, lx = lane & 3;
    uint32_t sb = s2u(smem);

    int ar = tid >> 1, ah = tid & 1;
    const char* aSrc = (const char*)(g_h + (size_t)(m0 + ar) * FF) + ah * 32;
    uint32_t aDst = (uint32_t)(ar * 80 + ah * 32);
    const char* bBase = (const char*)(wdh + ((size_t)e << 20) + n0);
    int id0 = tid, id1 = tid + 256;
    int bk0 = id0 >> 4, bc0 = (id0 & 15) * 16;
    int bk1 = id1 >> 4, bc1 = (id1 & 15) * 16;
    uint32_t bdst0 = (uint32_t)(F2_BOFF + bk0 * 272 + bc0);
    uint32_t bdst1 = (uint32_t)(F2_BOFF + bk1 * 272 + bc1);

    float acc[2][8][4];
#pragma unroll
    for (int a = 0; a < 2; a++)
#pragma unroll
        for (int b = 0; b < 8; b++)
#pragma unroll
            for (int c = 0; c < 4; c++) acc[a][b][c] = 0.f;

#define F2_LOAD(kt, slot) do { \
    uint32_t s_ = sb + (slot) * F2_STAGE; \
    const char* as_ = aSrc + (kt) * 64; \
    CP16(s_ + aDst, as_);  CP16(s_ + aDst + 16, as_ + 16); \
    CP16(s_ + bdst0, bBase + (size_t)((kt) * 32 + bk0) * 2048 + bc0); \
    CP16(s_ + bdst1, bBase + (size_t)((kt) * 32 + bk1) * 2048 + bc1); \
    CP_COMMIT(); \
} while (0)

    F2_LOAD(0, 0);
    F2_LOAD(1, 1);
    F2_LOAD(2, 2);

    uint32_t l16 = (uint32_t)(lane & 15), lh = (uint32_t)(lane >> 4) * 16;

    const int NIT = FF / 32;
#pragma unroll 1
    for (int kt = 0; kt < NIT; kt++) {
        if (kt < NIT - 2)       { CP_WAIT(2); }
        else if (kt == NIT - 2) { CP_WAIT(1); }
        else                    { CP_WAIT(0); }
        __syncthreads();
        if (kt + 3 < NIT) F2_LOAD(kt + 3, (kt + 3) & 3);

        uint32_t stg = sb + (kt & 3) * F2_STAGE;
#pragma unroll
        for (int ks = 0; ks < 2; ks++) {
            uint32_t a_fr[2][4];
#pragma unroll
            for (int mt = 0; mt < 2; mt++) {
                uint32_t aa = stg + (wm * 32 + mt * 16 + l16) * 80 + ks * 32 + lh;
                LDSM4(a_fr[mt][0], a_fr[mt][1], a_fr[mt][2], a_fr[mt][3], aa);
            }
#pragma unroll
            for (int nt = 0; nt < 4; nt++) {
                uint32_t ba = stg + F2_BOFF + (ks * 16 + l16) * 272 +
                              (wn * 64 + nt * 16) * 2 + lh;
                uint32_t b0, b1, b2, b3;
                LDSM4T(b0, b1, b2, b3, ba);
#pragma unroll
                for (int mt = 0; mt < 2; mt++) {
                    MMA_F16(acc[mt][nt*2],   a_fr[mt], b0, b1);
                    MMA_F16(acc[mt][nt*2+1], a_fr[mt], b2, b3);
                }
            }
        }
    }

    // RED epilogue: out[token] += y  (padded rows have h=0 -> add exact zeros)
#pragma unroll
    for (int mt = 0; mt < 2; mt++) {
        int r0 = m0 + wm * 32 + mt * 16 + ly;
        int t0 = g_token_of[r0], t1 = g_token_of[r0 + 8];
        float* o0 = out + (size_t)t0 * DD;
        float* o1 = out + (size_t)t1 * DD;
#pragma unroll
        for (int nt = 0; nt < 8; nt++) {
            int c = n0 + wn * 64 + nt * 8 + 2 * lx;
            float* A = acc[mt][nt];
            atomicAdd(o0 + c,     A[0]);
            atomicAdd(o0 + c + 1, A[1]);
            atomicAdd(o1 + c,     A[2]);
            atomicAdd(o1 + c + 1, A[3]);
        }
    }
}

// ---------------- launch ----------------
extern "C" void kernel_launch(void* const* d_in, const int* in_sizes, int n_in,
                              void* d_out, int out_size) {
    const float* x  = (const float*)d_in[0];
    const float* wr = (const float*)d_in[1];
    const float* wg = (const float*)d_in[2];
    const float* wu = (const float*)d_in[3];
    const float* wd = (const float*)d_in[4];
    float* out = (float*)d_out;

    cudaFuncSetAttribute(ff1_tc, cudaFuncAttributeMaxDynamicSharedMemorySize, 4 * F1_STAGE);
    cudaFuncSetAttribute(ff2_tc, cudaFuncAttributeMaxDynamicSharedMemorySize, 4 * F2_STAGE);

    prep_router<<<ROUTER_BLOCKS + CVT_GU_BLOCKS, 256>>>(x, wr, wg, wu);

    __half* xh_p;  cudaGetSymbolAddress((void**)&xh_p,  g_xh);
    __half* wgh_p; cudaGetSymbolAddress((void**)&wgh_p, g_wgh);
    __half* wuh_p; cudaGetSymbolAddress((void**)&wuh_p, g_wuh);
    __half* wdh_p; cudaGetSymbolAddress((void**)&wdh_p, g_wdh);

    {
        dim3 g(FF / 64, MTILES + AUX_Y);   // GEMM tiles + aux (out zero, wd cvt)
        ff1_tc<<<g, 256, 4 * F1_STAGE>>>(xh_p, wgh_p, wuh_p, wd, out);
    }
    {
        dim3 g(DD / 128, MTILES);
        ff2_tc<<<g, 256, 4 * F2_STAGE>>>(wdh_p, out);
    }
}

// round 17
// speedup vs baseline: 1.1211x; 1.1211x over previous
#include <cuda_runtime.h>
#include <cuda_fp16.h>
#include <math.h>
#include <stdint.h>

#define BB 4
#define TT 2048
#define DD 1024
#define EE 8
#define FF 1024
#define NTOK (BB*TT)           // 8192
#define NASG (NTOK*2)          // 16384
#define MAXA (NASG + EE*128)   // 17408
#define MTILES (MAXA/128)      // 136

#define ROUTER_BLOCKS (NTOK/8)            // 1024
#define CVT_GU_BLOCKS ((1 << 21) / 256)   // 8192 (wg+wu: 2^21 uint4 items)

// ff1 aux: zero out (2^21 uint4) + convert wd (2^20 uint4) = 3*2^20 items
#define AUX_ITEMS     (3 << 20)
#define AUX_PER_BLOCK 2048                // 256 threads x 8
#define AUX_BLOCKS    (AUX_ITEMS / AUX_PER_BLOCK)   // 1536
#define AUX_Y         (AUX_BLOCKS / 16)             // 96 extra grid.y rows

// ---------------- scratch (zero-initialized at module load) ----------------
__device__ int   g_counts[EE];
__device__ int   g_cursor[EE];
__device__ int   g_offsets[EE+1];
__device__ int   g_eidx[NASG];
__device__ float g_ew[NASG];
__device__ int   g_token_of[MAXA];     // padded rows stay 0 forever
__device__ float g_weight_of[MAXA];    // padded rows stay 0.0f forever
__device__ int   g_flag;

__device__ __half g_xh [(size_t)NTOK*DD];
__device__ __half g_wgh[(size_t)EE*DD*FF];
__device__ __half g_wuh[(size_t)EE*DD*FF];
__device__ __half g_wdh[(size_t)EE*FF*DD];
__device__ __half g_h  [(size_t)MAXA*FF];

// ---------------- PTX helpers ----------------
__device__ __forceinline__ uint32_t s2u(const void* p) {
    uint32_t a;
    asm("{ .reg .u64 t; cvta.to.shared.u64 t, %1; cvt.u32.u64 %0, t; }" : "=r"(a) : "l"(p));
    return a;
}
#define CP16(dst, src) \
    asm volatile("cp.async.cg.shared.global [%0], [%1], 16;" :: "r"(dst), "l"(src) : "memory")
#define CP_COMMIT() asm volatile("cp.async.commit_group;" ::: "memory")
#define CP_WAIT(N)  asm volatile("cp.async.wait_group %0;" :: "n"(N) : "memory")

#define LDSM4(r0, r1, r2, r3, a) \
    asm volatile("ldmatrix.sync.aligned.m8n8.x4.shared.b16 {%0,%1,%2,%3}, [%4];" \
        : "=r"(r0), "=r"(r1), "=r"(r2), "=r"(r3) : "r"(a))
#define LDSM4T(r0, r1, r2, r3, a) \
    asm volatile("ldmatrix.sync.aligned.m8n8.x4.trans.shared.b16 {%0,%1,%2,%3}, [%4];" \
        : "=r"(r0), "=r"(r1), "=r"(r2), "=r"(r3) : "r"(a))

// mma m16n8k16 fp16 in, fp32 acc
#define MMA_F16(d, a, b0, b1) \
    asm volatile("mma.sync.aligned.m16n8k16.row.col.f32.f16.f16.f32 " \
        "{%0,%1,%2,%3}, {%4,%5,%6,%7}, {%8,%9}, {%0,%1,%2,%3};" \
        : "+f"((d)[0]), "+f"((d)[1]), "+f"((d)[2]), "+f"((d)[3]) \
        : "r"((a)[0]), "r"((a)[1]), "r"((a)[2]), "r"((a)[3]), \
          "r"(b0), "r"(b1))

__device__ __forceinline__ uint32_t pack_h2(float a, float b) {
    __half2 h = __floats2half2_rn(a, b);
    return *(uint32_t*)&h;
}

// ============ prep + router fused (no smem) ============
// blocks [0, ROUTER_BLOCKS)     : router + fp16 x emit (wr read via L1)
// blocks [.., +CVT_GU_BLOCKS)   : wg/wu fp32->fp16, 2 float4 -> 1 uint4
__global__ void __launch_bounds__(256)
prep_router(const float* __restrict__ x,  const float* __restrict__ wr,
            const float* __restrict__ wg, const float* __restrict__ wu) {
    int tid = threadIdx.x;

    if (blockIdx.x < ROUTER_BLOCKS) {
        // ---------------- router ----------------
        int warp = tid >> 5, lane = tid & 31;
        int t = blockIdx.x * 8 + warp;
        const float* xr = x + (size_t)t * DD;

        float acc[EE];
#pragma unroll
        for (int e = 0; e < EE; e++) acc[e] = 0.f;
#pragma unroll
        for (int i = 0; i < 8; i++) {
            int d0 = i * 128 + lane * 4;
            float4 xv = *(const float4*)(xr + d0);
            uint2 pk = make_uint2(pack_h2(xv.x, xv.y), pack_h2(xv.z, xv.w));
            *(uint2*)(g_xh + (size_t)t * DD + d0) = pk;

            float xa[4] = { xv.x, xv.y, xv.z, xv.w };
#pragma unroll
            for (int j = 0; j < 4; j++) {
                const float4* wp = (const float4*)(wr + (size_t)(d0 + j) * EE);
                float4 w0 = wp[0], w1 = wp[1];
                acc[0] += xa[j] * w0.x;  acc[1] += xa[j] * w0.y;
                acc[2] += xa[j] * w0.z;  acc[3] += xa[j] * w0.w;
                acc[4] += xa[j] * w1.x;  acc[5] += xa[j] * w1.y;
                acc[6] += xa[j] * w1.z;  acc[7] += xa[j] * w1.w;
            }
        }
#pragma unroll
        for (int off = 16; off > 0; off >>= 1)
#pragma unroll
            for (int e = 0; e < EE; e++)
                acc[e] += __shfl_xor_sync(0xffffffffu, acc[e], off);

        if (lane == 0) {
            float m = acc[0];
#pragma unroll
            for (int e = 1; e < EE; e++) m = fmaxf(m, acc[e]);
            float p[EE], s = 0.f;
#pragma unroll
            for (int e = 0; e < EE; e++) { p[e] = expf(acc[e] - m); s += p[e]; }
            float inv = 1.f / s;
#pragma unroll
            for (int e = 0; e < EE; e++) p[e] *= inv;

            int be = 0; float b = p[0];
#pragma unroll
            for (int e = 1; e < EE; e++) if (p[e] > b) { b = p[e]; be = e; }
            int be2 = -1; float b2 = -1.f;
#pragma unroll
            for (int e = 0; e < EE; e++)
                if (e != be && p[e] > b2) { b2 = p[e]; be2 = e; }

            float w0 = 1.f / (1.f + expf(b2 - b));
            float w1 = 1.f - w0;

            g_eidx[2*t]   = be;   g_ew[2*t]   = w0;
            g_eidx[2*t+1] = be2;  g_ew[2*t+1] = w1;
            atomicAdd(&g_counts[be], 1);
            atomicAdd(&g_counts[be2], 1);
        }
    } else {
        // ---------------- wg/wu convert: 2 float4 -> 1 uint4 ----------------
        int idx = (blockIdx.x - ROUTER_BLOCKS) * 256 + tid;   // 0 .. 2^21-1
        int j = idx * 2;
        int region = j >> 21;
        int off = j & ((1 << 21) - 1);
        const float* src = region ? wu : wg;
        __half* dst = region ? g_wuh : g_wgh;
        float4 v0 = ((const float4*)src)[off];
        float4 v1 = ((const float4*)src)[off + 1];
        uint4 pk;
        pk.x = pack_h2(v0.x, v0.y);
        pk.y = pack_h2(v0.z, v0.w);
        pk.z = pack_h2(v1.x, v1.y);
        pk.w = pack_h2(v1.z, v1.w);
        ((uint4*)dst)[off >> 1] = pk;
    }
}

// ---------------- offsets + scatter fused ----------------
__global__ void offsets_scatter_kernel() {
    if (blockIdx.x == 0 && threadIdx.x == 0) {
        int off = 0;
#pragma unroll
        for (int e = 0; e < EE; e++) {
            g_offsets[e] = off;
            off += (g_counts[e] + 127) & ~127;
        }
        g_offsets[EE] = off;
        __threadfence();
        atomicExch(&g_flag, 1);
    }
    if (threadIdx.x == 0) {
        while (atomicAdd(&g_flag, 0) == 0) __nanosleep(64);
    }
    __syncthreads();

    int i = blockIdx.x * blockDim.x + threadIdx.x;
    if (i >= NASG) return;
    int e = g_eidx[i];
    int pos = atomicAdd(&g_cursor[e], 1);
    int a = g_offsets[e] + pos;
    g_token_of[a] = i >> 1;
    g_weight_of[a] = g_ew[i];
}

// ======================= ff1 : gate+up grouped GEMM (fp16 mma) ===============
// BM=128, BN=64 (two Bs), BK=32, 4 stages, 256 threads, warp tile 32x32. (R8)
// Extra grid.y rows (>= MTILES) are aux blocks: zero out + convert wd.
#define F1_STAGE 19456
#define F1_BOFF  10240

__global__ void __launch_bounds__(256, 2)
ff1_tc(const __half* __restrict__ xh,
       const __half* __restrict__ wgh,
       const __half* __restrict__ wuh,
       const float* __restrict__ wd,
       float* __restrict__ out) {
    int tid = threadIdx.x;

    // ---------------- aux blocks: zero out + wd fp32->fp16 ----------------
    if (blockIdx.y >= MTILES) {
        int bid = (blockIdx.y - MTILES) * gridDim.x + blockIdx.x;   // 0..1535
        int base = bid * AUX_PER_BLOCK + tid;
        const int OUTI = 1 << 21;   // out uint4 items
#pragma unroll
        for (int q = 0; q < 8; q++) {
            int item = base + q * 256;
            if (item < OUTI) {
                ((uint4*)out)[item] = make_uint4(0u, 0u, 0u, 0u);
            } else {
                int u = item - OUTI;            // 0 .. 2^20-1 : uint4 in g_wdh
                int off = u * 2;                // float4 index in wd
                float4 v0 = ((const float4*)wd)[off];
                float4 v1 = ((const float4*)wd)[off + 1];
                uint4 pk;
                pk.x = pack_h2(v0.x, v0.y);
                pk.y = pack_h2(v0.z, v0.w);
                pk.z = pack_h2(v1.x, v1.y);
                pk.w = pack_h2(v1.z, v1.w);
                ((uint4*)g_wdh)[u] = pk;
            }
        }
        return;
    }

    // reset routing counters for the NEXT launch (scatter is complete by now)
    if (blockIdx.x == 0 && blockIdx.y == 0 && tid < EE) {
        g_counts[tid] = 0;
        g_cursor[tid] = 0;
        if (tid == 0) g_flag = 0;
    }

    extern __shared__ char smem[];
    int m0 = blockIdx.y * 128;
    if (m0 >= g_offsets[EE]) return;
    int e = 0;
#pragma unroll
    for (int i = 0; i < EE; i++) if (m0 >= g_offsets[i+1]) e = i + 1;
    int n0 = blockIdx.x * 64;

    int wid = tid >> 5, lane = tid & 31;
    int wm = wid & 3, wn = wid >> 2;
    int ly = lane >> 2, lx = lane & 3;
    uint32_t sb = s2u(smem);

    int ar = tid >> 1, ah = tid & 1;
    int tok = g_token_of[m0 + ar];
    const char* aSrc = (const char*)(xh + (size_t)tok * DD) + ah * 32;
    uint32_t aDst = (uint32_t)(ar * 80 + ah * 32);
    const char* gBase = (const char*)(wgh + ((size_t)e << 20) + n0);
    const char* uBase = (const char*)(wuh + ((size_t)e << 20) + n0);
    int id0 = tid, id1 = tid + 256;
    int brow0 = id0 >> 3, bc0 = (id0 & 7) * 16;
    int brow1 = id1 >> 3, bc1 = (id1 & 7) * 16;
    int bmat0 = brow0 >> 5, bk0 = brow0 & 31;
    int bmat1 = brow1 >> 5, bk1 = brow1 & 31;
    const char* bsrc0 = (bmat0 ? uBase : gBase) + bc0;
    const char* bsrc1 = (bmat1 ? uBase : gBase) + bc1;
    uint32_t bdst0 = (uint32_t)(F1_BOFF + bmat0 * 4608 + bk0 * 144 + bc0);
    uint32_t bdst1 = (uint32_t)(F1_BOFF + bmat1 * 4608 + bk1 * 144 + bc1);

    float accG[2][4][4], accU[2][4][4];
#pragma unroll
    for (int a = 0; a < 2; a++)
#pragma unroll
        for (int b = 0; b < 4; b++)
#pragma unroll
            for (int c = 0; c < 4; c++) { accG[a][b][c] = 0.f; accU[a][b][c] = 0.f; }

#define F1_LOAD(kt, slot) do { \
    uint32_t s_ = sb + (slot) * F1_STAGE; \
    const char* as_ = aSrc + (kt) * 64; \
    CP16(s_ + aDst, as_);  CP16(s_ + aDst + 16, as_ + 16); \
    CP16(s_ + bdst0, bsrc0 + (size_t)((kt) * 32 + bk0) * 2048); \
    CP16(s_ + bdst1, bsrc1 + (size_t)((kt) * 32 + bk1) * 2048); \
    CP_COMMIT(); \
} while (0)

    F1_LOAD(0, 0);
    F1_LOAD(1, 1);
    F1_LOAD(2, 2);

    uint32_t l16 = (uint32_t)(lane & 15), lh = (uint32_t)(lane >> 4) * 16;

    const int NIT = DD / 32;
#pragma unroll 1
    for (int kt = 0; kt < NIT; kt++) {
        if (kt < NIT - 2)       { CP_WAIT(2); }
        else if (kt == NIT - 2) { CP_WAIT(1); }
        else                    { CP_WAIT(0); }
        __syncthreads();
        if (kt + 3 < NIT) F1_LOAD(kt + 3, (kt + 3) & 3);

        uint32_t stg = sb + (kt & 3) * F1_STAGE;
#pragma unroll
        for (int ks = 0; ks < 2; ks++) {
            uint32_t a_fr[2][4];
#pragma unroll
            for (int mt = 0; mt < 2; mt++) {
                uint32_t aa = stg + (wm * 32 + mt * 16 + l16) * 80 + ks * 32 + lh;
                LDSM4(a_fr[mt][0], a_fr[mt][1], a_fr[mt][2], a_fr[mt][3], aa);
            }
#pragma unroll
            for (int nt = 0; nt < 2; nt++) {
                uint32_t bg = stg + F1_BOFF + (ks * 16 + l16) * 144 +
                              (wn * 32 + nt * 16) * 2 + lh;
                uint32_t g0, g1, g2, g3, u0, u1, u2, u3;
                LDSM4T(g0, g1, g2, g3, bg);
                LDSM4T(u0, u1, u2, u3, bg + 4608);
#pragma unroll
                for (int mt = 0; mt < 2; mt++) {
                    MMA_F16(accG[mt][nt*2],   a_fr[mt], g0, g1);
                    MMA_F16(accG[mt][nt*2+1], a_fr[mt], g2, g3);
                    MMA_F16(accU[mt][nt*2],   a_fr[mt], u0, u1);
                    MMA_F16(accU[mt][nt*2+1], a_fr[mt], u2, u3);
                }
            }
        }
    }

    // epilogue: h = w * silu(g) * u -> fp16 (w = 0 on padded rows -> h = 0)
#pragma unroll
    for (int mt = 0; mt < 2; mt++) {
        int r0 = m0 + wm * 32 + mt * 16 + ly;
        float w0 = g_weight_of[r0], w1 = g_weight_of[r0 + 8];
#pragma unroll
        for (int nt = 0; nt < 4; nt++) {
            int c = n0 + wn * 32 + nt * 8 + 2 * lx;
            float* G = accG[mt][nt];
            float* U = accU[mt][nt];
            float h0 = w0 * (G[0] / (1.f + __expf(-G[0]))) * U[0];
            float h1 = w0 * (G[1] / (1.f + __expf(-G[1]))) * U[1];
            float h2 = w1 * (G[2] / (1.f + __expf(-G[2]))) * U[2];
            float h3 = w1 * (G[3] / (1.f + __expf(-G[3]))) * U[3];
            *(__half2*)(g_h + (size_t)r0 * FF + c)       = __floats2half2_rn(h0, h1);
            *(__half2*)(g_h + (size_t)(r0 + 8) * FF + c) = __floats2half2_rn(h2, h3);
        }
    }
}

// ======================= ff2 : down grouped GEMM (fp16 mma) ==================
// BM=128, BN=128, BK=32, 4 stages, warp tile 32x64. RED epilogue into out. (R8)
#define F2_STAGE 18944
#define F2_BOFF  10240

__global__ void __launch_bounds__(256, 2)
ff2_tc(const __half* __restrict__ wdh, float* __restrict__ out) {
    extern __shared__ char smem[];
    int m0 = blockIdx.y * 128;
    if (m0 >= g_offsets[EE]) return;
    int e = 0;
#pragma unroll
    for (int i = 0; i < EE; i++) if (m0 >= g_offsets[i+1]) e = i + 1;
    int n0 = blockIdx.x * 128;

    int tid = threadIdx.x, wid = tid >> 5, lane = tid & 31;
    int wm = wid & 3, wn = wid >> 2;
    int ly = lane >> 2, lx = lane & 3;
    uint32_t sb = s2u(smem);

    int ar = tid >> 1, ah = tid & 1;
    const char* aSrc = (const char*)(g_h + (size_t)(m0 + ar) * FF) + ah * 32;
    uint32_t aDst = (uint32_t)(ar * 80 + ah * 32);
    const char* bBase = (const char*)(wdh + ((size_t)e << 20) + n0);
    int id0 = tid, id1 = tid + 256;
    int bk0 = id0 >> 4, bc0 = (id0 & 15) * 16;
    int bk1 = id1 >> 4, bc1 = (id1 & 15) * 16;
    uint32_t bdst0 = (uint32_t)(F2_BOFF + bk0 * 272 + bc0);
    uint32_t bdst1 = (uint32_t)(F2_BOFF + bk1 * 272 + bc1);

    float acc[2][8][4];
#pragma unroll
    for (int a = 0; a < 2; a++)
#pragma unroll
        for (int b = 0; b < 8; b++)
#pragma unroll
            for (int c = 0; c < 4; c++) acc[a][b][c] = 0.f;

#define F2_LOAD(kt, slot) do { \
    uint32_t s_ = sb + (slot) * F2_STAGE; \
    const char* as_ = aSrc + (kt) * 64; \
    CP16(s_ + aDst, as_);  CP16(s_ + aDst + 16, as_ + 16); \
    CP16(s_ + bdst0, bBase + (size_t)((kt) * 32 + bk0) * 2048 + bc0); \
    CP16(s_ + bdst1, bBase + (size_t)((kt) * 32 + bk1) * 2048 + bc1); \
    CP_COMMIT(); \
} while (0)

    F2_LOAD(0, 0);
    F2_LOAD(1, 1);
    F2_LOAD(2, 2);

    uint32_t l16 = (uint32_t)(lane & 15), lh = (uint32_t)(lane >> 4) * 16;

    const int NIT = FF / 32;
#pragma unroll 1
    for (int kt = 0; kt < NIT; kt++) {
        if (kt < NIT - 2)       { CP_WAIT(2); }
        else if (kt == NIT - 2) { CP_WAIT(1); }
        else                    { CP_WAIT(0); }
        __syncthreads();
        if (kt + 3 < NIT) F2_LOAD(kt + 3, (kt + 3) & 3);

        uint32_t stg = sb + (kt & 3) * F2_STAGE;
#pragma unroll
        for (int ks = 0; ks < 2; ks++) {
            uint32_t a_fr[2][4];
#pragma unroll
            for (int mt = 0; mt < 2; mt++) {
                uint32_t aa = stg + (wm * 32 + mt * 16 + l16) * 80 + ks * 32 + lh;
                LDSM4(a_fr[mt][0], a_fr[mt][1], a_fr[mt][2], a_fr[mt][3], aa);
            }
#pragma unroll
            for (int nt = 0; nt < 4; nt++) {
                uint32_t ba = stg + F2_BOFF + (ks * 16 + l16) * 272 +
                              (wn * 64 + nt * 16) * 2 + lh;
                uint32_t b0, b1, b2, b3;
                LDSM4T(b0, b1, b2, b3, ba);
#pragma unroll
                for (int mt = 0; mt < 2; mt++) {
                    MMA_F16(acc[mt][nt*2],   a_fr[mt], b0, b1);
                    MMA_F16(acc[mt][nt*2+1], a_fr[mt], b2, b3);
                }
            }
        }
    }

    // RED epilogue: out[token] += y  (padded rows have h=0 -> add exact zeros)
#pragma unroll
    for (int mt = 0; mt < 2; mt++) {
        int r0 = m0 + wm * 32 + mt * 16 + ly;
        int t0 = g_token_of[r0], t1 = g_token_of[r0 + 8];
        float* o0 = out + (size_t)t0 * DD;
        float* o1 = out + (size_t)t1 * DD;
#pragma unroll
        for (int nt = 0; nt < 8; nt++) {
            int c = n0 + wn * 64 + nt * 8 + 2 * lx;
            float* A = acc[mt][nt];
            atomicAdd(o0 + c,     A[0]);
            atomicAdd(o0 + c + 1, A[1]);
            atomicAdd(o1 + c,     A[2]);
            atomicAdd(o1 + c + 1, A[3]);
        }
    }
}

// ---------------- launch ----------------
extern "C" void kernel_launch(void* const* d_in, const int* in_sizes, int n_in,
                              void* d_out, int out_size) {
    const float* x  = (const float*)d_in[0];
    const float* wr = (const float*)d_in[1];
    const float* wg = (const float*)d_in[2];
    const float* wu = (const float*)d_in[3];
    const float* wd = (const float*)d_in[4];
    float* out = (float*)d_out;

    cudaFuncSetAttribute(ff1_tc, cudaFuncAttributeMaxDynamicSharedMemorySize, 4 * F1_STAGE);
    cudaFuncSetAttribute(ff2_tc, cudaFuncAttributeMaxDynamicSharedMemorySize, 4 * F2_STAGE);

    prep_router<<<ROUTER_BLOCKS + CVT_GU_BLOCKS, 256>>>(x, wr, wg, wu);
    offsets_scatter_kernel<<<NASG / 256, 256>>>();

    __half* xh_p;  cudaGetSymbolAddress((void**)&xh_p,  g_xh);
    __half* wgh_p; cudaGetSymbolAddress((void**)&wgh_p, g_wgh);
    __half* wuh_p; cudaGetSymbolAddress((void**)&wuh_p, g_wuh);
    __half* wdh_p; cudaGetSymbolAddress((void**)&wdh_p, g_wdh);

    {
        dim3 g(FF / 64, MTILES + AUX_Y);   // GEMM tiles + aux (out zero, wd cvt)
        ff1_tc<<<g, 256, 4 * F1_STAGE>>>(xh_p, wgh_p, wuh_p, wd, out);
    }
    {
        dim3 g(DD / 128, MTILES);
        ff2_tc<<<g, 256, 4 * F2_STAGE>>>(wdh_p, out);
    }
}